// round 14
// baseline (speedup 1.0000x reference)
#include <cuda_runtime.h>

// out = relu( GroupNorm32( Wv @ feat + bv, gn_v_g, gn_v_b ) )
// (softmax-weighted sum in the reference is identity: v is constant along the
//  softmax axis and softmax rows sum to 1).
//
// feat [2,128,512], Wv [128,128], out [2,128,512].
// Grid: 64 blocks = B(2) x group(32); one CTA owns a full GN group.
// R13: OCCUPANCY experiment -- 1024 threads (32 warps/SM, 8 per SMSP; every
// prior round ran <=4/SMSP).  Thread = tx(128 float4 cols) x ty(8 cc-eighths)
// = 16 cc x 4 pts x 4 ch: 256 FMA-inst + 16 LDG.128, <=64 regs (single 8-slot
// buffer; second batch loaded as first-batch slots are consumed).
// part_s fold in two phases (ty4-7 store, ty0-3 accumulate) keeps smem 34KB.

#define C_CH     128
#define NPT      512
#define CH_PER_G 4
#define EPS_GN   1e-5f
#define NTHREADS 1024
#define ROW4     (NPT / 4)     // 128 float4 per feat row
#define CC_PER_T (C_CH / 8)    // 16 cc per ty
#define NWARPS   (NTHREADS / 32)

__device__ __forceinline__ float4 f4add(float4 a, float4 b) {
    a.x += b.x; a.y += b.y; a.z += b.z; a.w += b.w; return a;
}

#define FMA16(w, f)                                  \
    do {                                             \
        acc[0].x = fmaf((w).x, (f).x, acc[0].x);     \
        acc[0].y = fmaf((w).x, (f).y, acc[0].y);     \
        acc[0].z = fmaf((w).x, (f).z, acc[0].z);     \
        acc[0].w = fmaf((w).x, (f).w, acc[0].w);     \
        acc[1].x = fmaf((w).y, (f).x, acc[1].x);     \
        acc[1].y = fmaf((w).y, (f).y, acc[1].y);     \
        acc[1].z = fmaf((w).y, (f).z, acc[1].z);     \
        acc[1].w = fmaf((w).y, (f).w, acc[1].w);     \
        acc[2].x = fmaf((w).z, (f).x, acc[2].x);     \
        acc[2].y = fmaf((w).z, (f).y, acc[2].y);     \
        acc[2].z = fmaf((w).z, (f).z, acc[2].z);     \
        acc[2].w = fmaf((w).z, (f).w, acc[2].w);     \
        acc[3].x = fmaf((w).w, (f).x, acc[3].x);     \
        acc[3].y = fmaf((w).w, (f).y, acc[3].y);     \
        acc[3].z = fmaf((w).w, (f).z, acc[3].z);     \
        acc[3].w = fmaf((w).w, (f).w, acc[3].w);     \
    } while (0)

__global__ __launch_bounds__(NTHREADS, 1)
void fused_v_gn_relu_kernel(const float* __restrict__ feat,
                            const float* __restrict__ Wv,
                            const float* __restrict__ bv,
                            const float* __restrict__ gamma,
                            const float* __restrict__ beta,
                            float* __restrict__ out) {
    const int g  = blockIdx.x & 31;   // group 0..31
    const int b  = blockIdx.x >> 5;   // batch 0..1
    const int c0 = g * CH_PER_G;
    const int t  = threadIdx.x;       // 0..1023
    const int tx = t & 127;           // float4 column (0..127)
    const int ty = t >> 7;            // cc eighth (0..7)

    __shared__ float  wt_s[C_CH * CH_PER_G];          // transposed Wv, 2KB
    __shared__ float4 part_s[4 * CH_PER_G * ROW4];    // 4 slots after phase A, 32KB
    __shared__ float2 red_s[16];                      // warps 0..15 partials

    // Stage Wv transposed: wt_s[cc*4 + c] = Wv[(c0+c)*128 + cc].
    if (t < C_CH * CH_PER_G)
        wt_s[t] = Wv[(c0 + (t & 3)) * C_CH + (t >> 2)];

    // feat as float4 rows; this thread's column within its cc eighth.
    const float4* fp = (const float4*)(feat + (size_t)b * C_CH * NPT)
                       + (size_t)(ty * CC_PER_T) * ROW4 + tx;

    // Batch A: 8 loads issued before the sync (latency overlaps staging).
    float4 fb[8];
    #pragma unroll
    for (int i = 0; i < 8; i++) fb[i] = fp[i * ROW4];

    __syncthreads();

    const float4* wt4 = (const float4*)wt_s;
    const int wbase = ty * CC_PER_T;

    float4 acc[CH_PER_G];
    #pragma unroll
    for (int c = 0; c < CH_PER_G; c++) {
        acc[c].x = 0.f; acc[c].y = 0.f; acc[c].z = 0.f; acc[c].w = 0.f;
    }

    // Compute batch A; as each slot is consumed, refill it with batch B.
    #pragma unroll
    for (int i = 0; i < 8; i++) {
        const float4 w = wt4[wbase + i];        // broadcast LDS.128
        const float4 f = fb[i];
        fb[i] = fp[(8 + i) * ROW4];             // refill slot for batch B
        FMA16(w, f);
    }
    // Compute batch B.
    #pragma unroll
    for (int i = 0; i < 8; i++) {
        const float4 w = wt4[wbase + 8 + i];
        FMA16(w, fb[i]);
    }

    // Two-phase partial combine (keeps smem at 32KB for 8 ty slots):
    // Phase A: ty 4..7 store into slots 0..3.
    if (ty >= 4) {
        #pragma unroll
        for (int c = 0; c < CH_PER_G; c++)
            part_s[(ty - 4) * 512 + c * ROW4 + tx] = acc[c];
    }
    __syncthreads();
    // Phase B: ty 0..3 accumulate into the same slots.
    if (ty < 4) {
        #pragma unroll
        for (int c = 0; c < CH_PER_G; c++) {
            const int idx = ty * 512 + c * ROW4 + tx;
            part_s[idx] = f4add(part_s[idx], acc[c]);
        }
    }
    __syncthreads();

    // Threads 0..511 fold the 4 slots; warps 16..31 idle through the tail.
    float4 v;
    if (t < 512) {
        const float bvc = bv[c0 + (t >> 7)];
        v = f4add(f4add(part_s[t], part_s[t + 512]),
                  f4add(part_s[t + 1024], part_s[t + 1536]));
        v.x += bvc; v.y += bvc; v.z += bvc; v.w += bvc;

        float ps  = v.x + v.y + v.z + v.w;
        float pss = fmaf(v.x, v.x, fmaf(v.y, v.y,
                    fmaf(v.z, v.z, v.w * v.w)));
        #pragma unroll
        for (int off = 16; off > 0; off >>= 1) {
            ps  += __shfl_xor_sync(0xffffffffu, ps,  off);
            pss += __shfl_xor_sync(0xffffffffu, pss, off);
        }
        if ((t & 31) == 0) {
            float2 p; p.x = ps; p.y = pss;
            red_s[t >> 5] = p;
        }
    }
    __syncthreads();

    if (t < 512) {
        // Redundant fixed-order sum of the 16 warp partials.
        float ts = 0.f, tss = 0.f;
        #pragma unroll
        for (int w = 0; w < 16; w++) {
            const float2 p = red_s[w];
            ts  += p.x;
            tss += p.y;
        }
        const float inv_n = 1.0f / (float)(CH_PER_G * NPT);
        const float m     = ts * inv_n;
        const float var   = tss * inv_n - m * m;   // biased (jnp.var)
        const float rst   = rsqrtf(var + EPS_GN);

        const int   myc = c0 + (t >> 7);
        const float ga  = gamma[myc] * rst;
        const float be  = beta[myc];
        float4 y;
        y.x = fmaxf(fmaf(v.x - m, ga, be), 0.f);
        y.y = fmaxf(fmaf(v.y - m, ga, be), 0.f);
        y.z = fmaxf(fmaf(v.z - m, ga, be), 0.f);
        y.w = fmaxf(fmaf(v.w - m, ga, be), 0.f);
        float4* ob = (float4*)(out + (size_t)b * C_CH * NPT);
        ob[(size_t)myc * ROW4 + (t & 127)] = y;
    }
}

extern "C" void kernel_launch(void* const* d_in, const int* in_sizes, int n_in,
                              void* d_out, int out_size) {
    // metadata order:
    // 0 feat, 1 Wk, 2 bk, 3 Wq, 4 bq, 5 Wv, 6 bv, 7 gn_v_g, 8 gn_v_b,
    // 9 gn1_g, 10 gn1_b, 11 W1, 12 b1, 13 gn2_g, 14 gn2_b, 15 W2, 16 b2
    const float* feat = (const float*)d_in[0];
    const float* Wv   = (const float*)d_in[5];
    const float* bv   = (const float*)d_in[6];
    const float* gn_g = (const float*)d_in[7];
    const float* gn_b = (const float*)d_in[8];
    float* out = (float*)d_out;

    (void)in_sizes; (void)n_in; (void)out_size;

    fused_v_gn_relu_kernel<<<64, NTHREADS>>>(feat, Wv, bv, gn_g, gn_b, out);
}